// round 3
// baseline (speedup 1.0000x reference)
#include <cuda_runtime.h>

// ---------------- problem constants (fixed shapes) ----------------
#define NN   50000    // nodes
#define MM   200000   // incidences
#define EE   10000    // hyperedges
#define DN_  256
#define DHA_ 64
#define DH_  256
#define DIN_ 320      // DHA + DH

#define ROWS 64       // incidence rows per block
#define KB   32       // K-chunk staged in smem

// ---------------- device scratch (no allocations allowed) ----------------
__device__ float g_agg[(size_t)EE * DH_];   // hyperedge accumulator (10.2 MB)
__device__ float g_acc[(size_t)NN * DN_];   // node accumulator (51.2 MB)
__device__ float g_deg[NN];                 // node degree

// =====================================================================
// Kernel 1: node -> hyperedge.
// Per block: 64 incidences. gather x -> GEMM1 -> LN+ReLU -> GEMM2 -> RED agg_e
// thread layout: ty = tid>>5 (0..7) owns rows ty*8..ty*8+7, tx = tid&31 owns
// cols tx*8..tx*8+7.  A-loads broadcast within a warp (ty uniform per warp).
// =====================================================================
__global__ __launch_bounds__(256, 1)
void k_n2e(const float* __restrict__ x,
           const int*   __restrict__ node_ids,
           const int*   __restrict__ he_ids,
           const float* __restrict__ w1, const float* __restrict__ b1,
           const float* __restrict__ lng, const float* __restrict__ lnb,
           const float* __restrict__ w2, const float* __restrict__ b2)
{
    extern __shared__ char smem_raw[];
    float* xs = (float*)smem_raw;          // [64][256]
    float* hs = xs + ROWS * DN_;           // [64][256]
    float* ws = hs + ROWS * DH_;           // [32][256]
    int*   eid_s = (int*)(ws + KB * DH_);  // [64]
    int*   nid_s = eid_s + ROWS;           // [64]

    const int tid = threadIdx.x;
    const int ty = tid >> 5, tx = tid & 31, lane = tid & 31, wrp = tid >> 5;
    const int m0 = blockIdx.x * ROWS;

    if (tid < ROWS) {
        eid_s[tid] = he_ids[m0 + tid];
        nid_s[tid] = node_ids[m0 + tid];
    }
    __syncthreads();

    // gather x rows (float4, coalesced per row)
    for (int i = tid; i < ROWS * (DN_ / 4); i += 256) {
        int r = i >> 6, c4 = i & 63;
        float4 v = __ldg((const float4*)&x[(size_t)nid_s[r] * DN_ + c4 * 4]);
        *(float4*)&xs[r * DN_ + c4 * 4] = v;
    }
    __syncthreads();

    float acc[8][8];

    // ---------------- GEMM1: h = xs @ w1 + b1 ----------------
    {
        float4 bb0 = __ldg((const float4*)&b1[tx * 8]);
        float4 bb1 = __ldg((const float4*)&b1[tx * 8 + 4]);
        #pragma unroll
        for (int r = 0; r < 8; r++) {
            acc[r][0]=bb0.x; acc[r][1]=bb0.y; acc[r][2]=bb0.z; acc[r][3]=bb0.w;
            acc[r][4]=bb1.x; acc[r][5]=bb1.y; acc[r][6]=bb1.z; acc[r][7]=bb1.w;
        }
        for (int kc = 0; kc < DN_ / KB; kc++) {
            for (int i = tid; i < KB * (DH_ / 4); i += 256) {
                int kr = i >> 6, c4 = i & 63;
                *(float4*)&ws[kr * DH_ + c4 * 4] =
                    __ldg((const float4*)&w1[(size_t)(kc * KB + kr) * DH_ + c4 * 4]);
            }
            __syncthreads();
            #pragma unroll 4
            for (int k = 0; k < KB; k++) {
                float a[8];
                #pragma unroll
                for (int r = 0; r < 8; r++) a[r] = xs[(ty * 8 + r) * DN_ + kc * KB + k];
                float4 b0 = *(const float4*)&ws[k * DH_ + tx * 8];
                float4 b1v = *(const float4*)&ws[k * DH_ + tx * 8 + 4];
                #pragma unroll
                for (int r = 0; r < 8; r++) {
                    acc[r][0] += a[r] * b0.x;  acc[r][1] += a[r] * b0.y;
                    acc[r][2] += a[r] * b0.z;  acc[r][3] += a[r] * b0.w;
                    acc[r][4] += a[r] * b1v.x; acc[r][5] += a[r] * b1v.y;
                    acc[r][6] += a[r] * b1v.z; acc[r][7] += a[r] * b1v.w;
                }
            }
            __syncthreads();
        }
        #pragma unroll
        for (int r = 0; r < 8; r++) {
            *(float4*)&hs[(ty * 8 + r) * DH_ + tx * 8]     = make_float4(acc[r][0],acc[r][1],acc[r][2],acc[r][3]);
            *(float4*)&hs[(ty * 8 + r) * DH_ + tx * 8 + 4] = make_float4(acc[r][4],acc[r][5],acc[r][6],acc[r][7]);
        }
    }
    __syncthreads();

    // ---------------- LayerNorm + ReLU (warp per row) ----------------
    for (int rr = wrp * 8; rr < wrp * 8 + 8; rr++) {
        float v[8], s = 0.f, sq = 0.f;
        #pragma unroll
        for (int j = 0; j < 8; j++) {
            v[j] = hs[rr * DH_ + lane + j * 32];
            s += v[j]; sq += v[j] * v[j];
        }
        #pragma unroll
        for (int o = 16; o; o >>= 1) {
            s  += __shfl_xor_sync(0xffffffffu, s, o);
            sq += __shfl_xor_sync(0xffffffffu, sq, o);
        }
        float mu = s * (1.f / DH_);
        float var = sq * (1.f / DH_) - mu * mu;
        float rs = rsqrtf(var + 1e-5f);
        #pragma unroll
        for (int j = 0; j < 8; j++) {
            int c = lane + j * 32;
            float t = (v[j] - mu) * rs * __ldg(&lng[c]) + __ldg(&lnb[c]);
            hs[rr * DH_ + c] = fmaxf(t, 0.f);
        }
    }
    __syncthreads();

    // ---------------- GEMM2: msgs = hs @ w2 + b2 -> RED into g_agg ----------------
    {
        float4 bb0 = __ldg((const float4*)&b2[tx * 8]);
        float4 bb1 = __ldg((const float4*)&b2[tx * 8 + 4]);
        #pragma unroll
        for (int r = 0; r < 8; r++) {
            acc[r][0]=bb0.x; acc[r][1]=bb0.y; acc[r][2]=bb0.z; acc[r][3]=bb0.w;
            acc[r][4]=bb1.x; acc[r][5]=bb1.y; acc[r][6]=bb1.z; acc[r][7]=bb1.w;
        }
        for (int kc = 0; kc < DH_ / KB; kc++) {
            for (int i = tid; i < KB * (DH_ / 4); i += 256) {
                int kr = i >> 6, c4 = i & 63;
                *(float4*)&ws[kr * DH_ + c4 * 4] =
                    __ldg((const float4*)&w2[(size_t)(kc * KB + kr) * DH_ + c4 * 4]);
            }
            __syncthreads();
            #pragma unroll 4
            for (int k = 0; k < KB; k++) {
                float a[8];
                #pragma unroll
                for (int r = 0; r < 8; r++) a[r] = hs[(ty * 8 + r) * DH_ + kc * KB + k];
                float4 b0 = *(const float4*)&ws[k * DH_ + tx * 8];
                float4 b1v = *(const float4*)&ws[k * DH_ + tx * 8 + 4];
                #pragma unroll
                for (int r = 0; r < 8; r++) {
                    acc[r][0] += a[r] * b0.x;  acc[r][1] += a[r] * b0.y;
                    acc[r][2] += a[r] * b0.z;  acc[r][3] += a[r] * b0.w;
                    acc[r][4] += a[r] * b1v.x; acc[r][5] += a[r] * b1v.y;
                    acc[r][6] += a[r] * b1v.z; acc[r][7] += a[r] * b1v.w;
                }
            }
            __syncthreads();
        }
        #pragma unroll
        for (int r = 0; r < 8; r++) {
            int e = eid_s[ty * 8 + r];
            float* dst = &g_agg[(size_t)e * DH_ + tx * 8];
            #pragma unroll
            for (int c = 0; c < 8; c++) atomicAdd(&dst[c], acc[r][c]);
        }
    }
}

// =====================================================================
// Kernel 2: hyperedge -> node.
// gather [he_attr | agg_e/(cnt+eps)] (320 wide) -> GEMM(K=320) -> LN+ReLU
// -> GEMM -> ReLU -> RED into g_acc, count degrees.
// =====================================================================
__global__ __launch_bounds__(256, 1)
void k_e2n(const int*   __restrict__ node_ids,
           const int*   __restrict__ he_ids,
           const float* __restrict__ he_attr,
           const float* __restrict__ he_count,
           const float* __restrict__ w1, const float* __restrict__ b1,
           const float* __restrict__ lng, const float* __restrict__ lnb,
           const float* __restrict__ w2, const float* __restrict__ b2)
{
    extern __shared__ char smem_raw[];
    float* as = (float*)smem_raw;            // [64][320]
    float* gs = as + ROWS * DIN_;            // [64][256]
    float* ws = gs + ROWS * DH_;             // [32][256]
    int*   eid_s = (int*)(ws + KB * DH_);    // [64]
    int*   nid_s = eid_s + ROWS;             // [64]
    float* rc_s  = (float*)(nid_s + ROWS);   // [64]

    const int tid = threadIdx.x;
    const int ty = tid >> 5, tx = tid & 31, lane = tid & 31, wrp = tid >> 5;
    const int m0 = blockIdx.x * ROWS;

    if (tid < ROWS) {
        int e = he_ids[m0 + tid];
        eid_s[tid] = e;
        nid_s[tid] = node_ids[m0 + tid];
        rc_s[tid]  = 1.f / (he_count[e] + 1e-6f);
    }
    __syncthreads();

    // gather he_attr part (64 cols)
    for (int i = tid; i < ROWS * (DHA_ / 4); i += 256) {
        int r = i >> 4, c4 = i & 15;
        float4 v = __ldg((const float4*)&he_attr[(size_t)eid_s[r] * DHA_ + c4 * 4]);
        *(float4*)&as[r * DIN_ + c4 * 4] = v;
    }
    // gather normalized agg part (256 cols)
    for (int i = tid; i < ROWS * (DH_ / 4); i += 256) {
        int r = i >> 6, c4 = i & 63;
        float rc = rc_s[r];
        float4 v = *(const float4*)&g_agg[(size_t)eid_s[r] * DH_ + c4 * 4];
        v.x *= rc; v.y *= rc; v.z *= rc; v.w *= rc;
        *(float4*)&as[r * DIN_ + DHA_ + c4 * 4] = v;
    }
    __syncthreads();

    float acc[8][8];

    // ---------------- GEMM1: g = as @ w1 + b1 (K = 320) ----------------
    {
        float4 bb0 = __ldg((const float4*)&b1[tx * 8]);
        float4 bb1 = __ldg((const float4*)&b1[tx * 8 + 4]);
        #pragma unroll
        for (int r = 0; r < 8; r++) {
            acc[r][0]=bb0.x; acc[r][1]=bb0.y; acc[r][2]=bb0.z; acc[r][3]=bb0.w;
            acc[r][4]=bb1.x; acc[r][5]=bb1.y; acc[r][6]=bb1.z; acc[r][7]=bb1.w;
        }
        for (int kc = 0; kc < DIN_ / KB; kc++) {
            for (int i = tid; i < KB * (DH_ / 4); i += 256) {
                int kr = i >> 6, c4 = i & 63;
                *(float4*)&ws[kr * DH_ + c4 * 4] =
                    __ldg((const float4*)&w1[(size_t)(kc * KB + kr) * DH_ + c4 * 4]);
            }
            __syncthreads();
            #pragma unroll 4
            for (int k = 0; k < KB; k++) {
                float a[8];
                #pragma unroll
                for (int r = 0; r < 8; r++) a[r] = as[(ty * 8 + r) * DIN_ + kc * KB + k];
                float4 b0 = *(const float4*)&ws[k * DH_ + tx * 8];
                float4 b1v = *(const float4*)&ws[k * DH_ + tx * 8 + 4];
                #pragma unroll
                for (int r = 0; r < 8; r++) {
                    acc[r][0] += a[r] * b0.x;  acc[r][1] += a[r] * b0.y;
                    acc[r][2] += a[r] * b0.z;  acc[r][3] += a[r] * b0.w;
                    acc[r][4] += a[r] * b1v.x; acc[r][5] += a[r] * b1v.y;
                    acc[r][6] += a[r] * b1v.z; acc[r][7] += a[r] * b1v.w;
                }
            }
            __syncthreads();
        }
        #pragma unroll
        for (int r = 0; r < 8; r++) {
            *(float4*)&gs[(ty * 8 + r) * DH_ + tx * 8]     = make_float4(acc[r][0],acc[r][1],acc[r][2],acc[r][3]);
            *(float4*)&gs[(ty * 8 + r) * DH_ + tx * 8 + 4] = make_float4(acc[r][4],acc[r][5],acc[r][6],acc[r][7]);
        }
    }
    __syncthreads();

    // ---------------- LayerNorm + ReLU ----------------
    for (int rr = wrp * 8; rr < wrp * 8 + 8; rr++) {
        float v[8], s = 0.f, sq = 0.f;
        #pragma unroll
        for (int j = 0; j < 8; j++) {
            v[j] = gs[rr * DH_ + lane + j * 32];
            s += v[j]; sq += v[j] * v[j];
        }
        #pragma unroll
        for (int o = 16; o; o >>= 1) {
            s  += __shfl_xor_sync(0xffffffffu, s, o);
            sq += __shfl_xor_sync(0xffffffffu, sq, o);
        }
        float mu = s * (1.f / DH_);
        float var = sq * (1.f / DH_) - mu * mu;
        float rs = rsqrtf(var + 1e-5f);
        #pragma unroll
        for (int j = 0; j < 8; j++) {
            int c = lane + j * 32;
            float t = (v[j] - mu) * rs * __ldg(&lng[c]) + __ldg(&lnb[c]);
            gs[rr * DH_ + c] = fmaxf(t, 0.f);
        }
    }
    __syncthreads();

    // ---------------- GEMM2: msg = relu(gs @ w2 + b2) -> RED into g_acc ----------------
    {
        float4 bb0 = __ldg((const float4*)&b2[tx * 8]);
        float4 bb1 = __ldg((const float4*)&b2[tx * 8 + 4]);
        #pragma unroll
        for (int r = 0; r < 8; r++) {
            acc[r][0]=bb0.x; acc[r][1]=bb0.y; acc[r][2]=bb0.z; acc[r][3]=bb0.w;
            acc[r][4]=bb1.x; acc[r][5]=bb1.y; acc[r][6]=bb1.z; acc[r][7]=bb1.w;
        }
        for (int kc = 0; kc < DH_ / KB; kc++) {
            for (int i = tid; i < KB * (DN_ / 4); i += 256) {
                int kr = i >> 6, c4 = i & 63;
                *(float4*)&ws[kr * DN_ + c4 * 4] =
                    __ldg((const float4*)&w2[(size_t)(kc * KB + kr) * DN_ + c4 * 4]);
            }
            __syncthreads();
            #pragma unroll 4
            for (int k = 0; k < KB; k++) {
                float a[8];
                #pragma unroll
                for (int r = 0; r < 8; r++) a[r] = gs[(ty * 8 + r) * DH_ + kc * KB + k];
                float4 b0 = *(const float4*)&ws[k * DN_ + tx * 8];
                float4 b1v = *(const float4*)&ws[k * DN_ + tx * 8 + 4];
                #pragma unroll
                for (int r = 0; r < 8; r++) {
                    acc[r][0] += a[r] * b0.x;  acc[r][1] += a[r] * b0.y;
                    acc[r][2] += a[r] * b0.z;  acc[r][3] += a[r] * b0.w;
                    acc[r][4] += a[r] * b1v.x; acc[r][5] += a[r] * b1v.y;
                    acc[r][6] += a[r] * b1v.z; acc[r][7] += a[r] * b1v.w;
                }
            }
            __syncthreads();
        }
        if (tx == 0) {
            #pragma unroll
            for (int r = 0; r < 8; r++) atomicAdd(&g_deg[nid_s[ty * 8 + r]], 1.f);
        }
        #pragma unroll
        for (int r = 0; r < 8; r++) {
            int n = nid_s[ty * 8 + r];
            float* dst = &g_acc[(size_t)n * DN_ + tx * 8];
            #pragma unroll
            for (int c = 0; c < 8; c++) atomicAdd(&dst[c], fmaxf(acc[r][c], 0.f));
        }
    }
}

// =====================================================================
// Kernel 3: out = x + LN(g_acc / (deg + eps)).  Warp per node row.
// =====================================================================
__global__ __launch_bounds__(256, 4)
void k_final(const float* __restrict__ x,
             const float* __restrict__ lng, const float* __restrict__ lnb,
             float* __restrict__ out)
{
    const int lane = threadIdx.x & 31;
    const int n = blockIdx.x * 8 + (threadIdx.x >> 5);
    if (n >= NN) return;

    float rd = 1.f / (g_deg[n] + 1e-6f);
    float v[8], s = 0.f, sq = 0.f;
    #pragma unroll
    for (int j = 0; j < 8; j++) {
        v[j] = g_acc[(size_t)n * DN_ + lane + j * 32] * rd;
        s += v[j]; sq += v[j] * v[j];
    }
    #pragma unroll
    for (int o = 16; o; o >>= 1) {
        s  += __shfl_xor_sync(0xffffffffu, s, o);
        sq += __shfl_xor_sync(0xffffffffu, sq, o);
    }
    float mu = s * (1.f / DN_);
    float var = sq * (1.f / DN_) - mu * mu;
    float rs = rsqrtf(var + 1e-5f);
    #pragma unroll
    for (int j = 0; j < 8; j++) {
        int c = lane + j * 32;
        float t = (v[j] - mu) * rs * __ldg(&lng[c]) + __ldg(&lnb[c]);
        out[(size_t)n * DN_ + c] = __ldg(&x[(size_t)n * DN_ + c]) + t;
    }
}

// =====================================================================
// launcher
// =====================================================================
extern "C" void kernel_launch(void* const* d_in, const int* in_sizes, int n_in,
                              void* d_out, int out_size)
{
    const float* x        = (const float*)d_in[0];
    const int*   node_ids = (const int*)  d_in[1];
    const int*   he_ids   = (const int*)  d_in[2];
    const float* he_attr  = (const float*)d_in[3];
    const float* he_count = (const float*)d_in[4];
    const float* n2e_w1   = (const float*)d_in[5];
    const float* n2e_b1   = (const float*)d_in[6];
    const float* n2e_lng  = (const float*)d_in[7];
    const float* n2e_lnb  = (const float*)d_in[8];
    const float* n2e_w2   = (const float*)d_in[9];
    const float* n2e_b2   = (const float*)d_in[10];
    const float* e2n_w1   = (const float*)d_in[11];
    const float* e2n_b1   = (const float*)d_in[12];
    const float* e2n_lng  = (const float*)d_in[13];
    const float* e2n_lnb  = (const float*)d_in[14];
    const float* e2n_w2   = (const float*)d_in[15];
    const float* e2n_b2   = (const float*)d_in[16];
    const float* ln_g     = (const float*)d_in[17];
    const float* ln_b     = (const float*)d_in[18];
    float* out = (float*)d_out;

    void *p_agg, *p_acc, *p_deg;
    cudaGetSymbolAddress(&p_agg, g_agg);
    cudaGetSymbolAddress(&p_acc, g_acc);
    cudaGetSymbolAddress(&p_deg, g_deg);
    cudaMemsetAsync(p_agg, 0, sizeof(float) * (size_t)EE * DH_);
    cudaMemsetAsync(p_acc, 0, sizeof(float) * (size_t)NN * DN_);
    cudaMemsetAsync(p_deg, 0, sizeof(float) * NN);

    // dynamic smem sizes
    const int smem1 = (ROWS * DN_ + ROWS * DH_ + KB * DH_) * 4 + 2 * ROWS * 4;         // ~164.4 KB
    const int smem2 = (ROWS * DIN_ + ROWS * DH_ + KB * DH_) * 4 + 3 * ROWS * 4;        // ~181.0 KB
    cudaFuncSetAttribute(k_n2e, cudaFuncAttributeMaxDynamicSharedMemorySize, smem1);
    cudaFuncSetAttribute(k_e2n, cudaFuncAttributeMaxDynamicSharedMemorySize, smem2);

    k_n2e<<<MM / ROWS, 256, smem1>>>(x, node_ids, he_ids,
                                     n2e_w1, n2e_b1, n2e_lng, n2e_lnb, n2e_w2, n2e_b2);
    k_e2n<<<MM / ROWS, 256, smem2>>>(node_ids, he_ids, he_attr, he_count,
                                     e2n_w1, e2n_b1, e2n_lng, e2n_lnb, e2n_w2, e2n_b2);
    k_final<<<(NN + 7) / 8, 256>>>(x, ln_g, ln_b, out);
}

// round 4
// speedup vs baseline: 1.4451x; 1.4451x over previous
#include <cuda_runtime.h>

// ---------------- problem constants (fixed shapes) ----------------
#define NN   50000    // nodes
#define MM   200000   // incidences
#define EE   10000    // hyperedges
#define DN_  256
#define DHA_ 64
#define DH_  256
#define DIN_ 320      // DHA + DH

#define ROWS 64       // incidence rows per block
#define KB   16       // K-chunk staged in smem

typedef unsigned long long u64;

// ---------------- device scratch (no allocations allowed) ----------------
__device__ float g_agg[(size_t)EE * DH_];   // hyperedge accumulator (10.2 MB)
__device__ float g_acc[(size_t)NN * DN_];   // node accumulator (51.2 MB)
__device__ float g_deg[NN];                 // node degree

// ---------------- packed f32x2 helpers ----------------
__device__ __forceinline__ u64 pk2(float x) {
    u64 r; asm("mov.b64 %0, {%1, %1};" : "=l"(r) : "f"(x)); return r;
}
__device__ __forceinline__ void ffma2(u64& d, u64 a, u64 b) {
    asm("fma.rn.f32x2 %0, %1, %2, %0;" : "+l"(d) : "l"(a), "l"(b));
}
__device__ __forceinline__ float2 upk(u64 p) {
    float2 r; asm("mov.b64 {%0, %1}, %2;" : "=f"(r.x), "=f"(r.y) : "l"(p)); return r;
}
__device__ __forceinline__ void red4(float* p, float a, float b, float c, float d) {
    asm volatile("red.global.add.v4.f32 [%0], {%1, %2, %3, %4};"
                 :: "l"(p), "f"(a), "f"(b), "f"(c), "f"(d) : "memory");
}

// ---------------- generic fused GEMM tile: acc += A_sm[rows,KTOT] @ W_gm[KTOT,256] ----------------
// thread (ty,tx): rows ty*8..+7, cols tx*8..+7 packed as 4 x f32x2.
template<int KTOT, int LDA>
__device__ __forceinline__ void gemm_tile(const float* __restrict__ A_sm,
                                          const float* __restrict__ W_gm,
                                          float* ws, u64 acc[8][4],
                                          int tid, int ty, int tx)
{
    #pragma unroll 1
    for (int kc = 0; kc < KTOT / KB; kc++) {
        // stage weights [KB,256]
        #pragma unroll
        for (int i = tid; i < KB * (DH_ / 4); i += 256) {
            int kr = i >> 6, c4 = i & 63;
            *(float4*)&ws[kr * DH_ + c4 * 4] =
                __ldg((const float4*)&W_gm[(size_t)(kc * KB + kr) * DH_ + c4 * 4]);
        }
        __syncthreads();
        #pragma unroll
        for (int k2 = 0; k2 < KB / 2; k2++) {
            ulonglong2 wa = *(const ulonglong2*)&ws[(2 * k2)     * DH_ + tx * 8];
            ulonglong2 wb = *(const ulonglong2*)&ws[(2 * k2)     * DH_ + tx * 8 + 4];
            ulonglong2 wc = *(const ulonglong2*)&ws[(2 * k2 + 1) * DH_ + tx * 8];
            ulonglong2 wd = *(const ulonglong2*)&ws[(2 * k2 + 1) * DH_ + tx * 8 + 4];
            #pragma unroll
            for (int r = 0; r < 8; r++) {
                float2 a2 = *(const float2*)&A_sm[(ty * 8 + r) * LDA + kc * KB + 2 * k2];
                u64 ap0 = pk2(a2.x), ap1 = pk2(a2.y);
                ffma2(acc[r][0], ap0, wa.x); ffma2(acc[r][1], ap0, wa.y);
                ffma2(acc[r][2], ap0, wb.x); ffma2(acc[r][3], ap0, wb.y);
                ffma2(acc[r][0], ap1, wc.x); ffma2(acc[r][1], ap1, wc.y);
                ffma2(acc[r][2], ap1, wd.x); ffma2(acc[r][3], ap1, wd.y);
            }
        }
        __syncthreads();
    }
}

__device__ __forceinline__ void init_bias(const float* __restrict__ b, int tx, u64 acc[8][4]) {
    u64 b0 = __ldg((const u64*)&b[tx * 8]);
    u64 b1 = __ldg((const u64*)&b[tx * 8 + 2]);
    u64 b2 = __ldg((const u64*)&b[tx * 8 + 4]);
    u64 b3 = __ldg((const u64*)&b[tx * 8 + 6]);
    #pragma unroll
    for (int r = 0; r < 8; r++) { acc[r][0] = b0; acc[r][1] = b1; acc[r][2] = b2; acc[r][3] = b3; }
}

// LayerNorm + ReLU over [ROWS,256] in smem, warp per row
__device__ __forceinline__ void ln_relu(float* hs, const float* __restrict__ lng,
                                        const float* __restrict__ lnb, int lane, int wrp)
{
    for (int rr = wrp * 8; rr < wrp * 8 + 8; rr++) {
        float v[8], s = 0.f, sq = 0.f;
        #pragma unroll
        for (int j = 0; j < 8; j++) {
            v[j] = hs[rr * DH_ + lane + j * 32];
            s += v[j]; sq += v[j] * v[j];
        }
        #pragma unroll
        for (int o = 16; o; o >>= 1) {
            s  += __shfl_xor_sync(0xffffffffu, s, o);
            sq += __shfl_xor_sync(0xffffffffu, sq, o);
        }
        float mu = s * (1.f / DH_);
        float var = sq * (1.f / DH_) - mu * mu;
        float rs = rsqrtf(var + 1e-5f);
        #pragma unroll
        for (int j = 0; j < 8; j++) {
            int c = lane + j * 32;
            float t = (v[j] - mu) * rs * __ldg(&lng[c]) + __ldg(&lnb[c]);
            hs[rr * DH_ + c] = fmaxf(t, 0.f);
        }
    }
}

// =====================================================================
// Kernel 1: node -> hyperedge.
// smem: xs [64][256] (aliased by hs after GEMM1) + ws [16][256] + ids
// =====================================================================
__global__ __launch_bounds__(256, 2)
void k_n2e(const float* __restrict__ x,
           const int*   __restrict__ node_ids,
           const int*   __restrict__ he_ids,
           const float* __restrict__ w1, const float* __restrict__ b1,
           const float* __restrict__ lng, const float* __restrict__ lnb,
           const float* __restrict__ w2, const float* __restrict__ b2)
{
    extern __shared__ char smem_raw[];
    float* xs = (float*)smem_raw;          // [64][256]; hs aliases this after GEMM1
    float* ws = xs + ROWS * DN_;           // [16][256]
    int*   eid_s = (int*)(ws + KB * DH_);  // [64]
    int*   nid_s = eid_s + ROWS;           // [64]
    float* hs = xs;

    const int tid = threadIdx.x;
    const int ty = tid >> 5, tx = tid & 31;
    const int m0 = blockIdx.x * ROWS;

    if (tid < ROWS) {
        eid_s[tid] = he_ids[m0 + tid];
        nid_s[tid] = node_ids[m0 + tid];
    }
    __syncthreads();

    // gather x rows (float4, coalesced per row)
    for (int i = tid; i < ROWS * (DN_ / 4); i += 256) {
        int r = i >> 6, c4 = i & 63;
        float4 v = __ldg((const float4*)&x[(size_t)nid_s[r] * DN_ + c4 * 4]);
        *(float4*)&xs[r * DN_ + c4 * 4] = v;
    }
    __syncthreads();

    u64 acc[8][4];

    // GEMM1: h = xs @ w1 + b1
    init_bias(b1, tx, acc);
    gemm_tile<DN_, DN_>(xs, w1, ws, acc, tid, ty, tx);
    __syncthreads();   // everyone done reading xs before alias-overwrite
    #pragma unroll
    for (int r = 0; r < 8; r++) {
        ulonglong2* dst = (ulonglong2*)&hs[(ty * 8 + r) * DH_ + tx * 8];
        dst[0] = make_ulonglong2(acc[r][0], acc[r][1]);
        dst[1] = make_ulonglong2(acc[r][2], acc[r][3]);
    }
    __syncthreads();

    ln_relu(hs, lng, lnb, tx, ty);
    __syncthreads();

    // GEMM2: msgs = hs @ w2 + b2 -> RED into g_agg
    init_bias(b2, tx, acc);
    gemm_tile<DH_, DH_>(hs, w2, ws, acc, tid, ty, tx);

    #pragma unroll
    for (int r = 0; r < 8; r++) {
        int e = eid_s[ty * 8 + r];
        float* dst = &g_agg[(size_t)e * DH_ + tx * 8];
        float2 p0 = upk(acc[r][0]), p1 = upk(acc[r][1]);
        float2 p2 = upk(acc[r][2]), p3 = upk(acc[r][3]);
        red4(dst,     p0.x, p0.y, p1.x, p1.y);
        red4(dst + 4, p2.x, p2.y, p3.x, p3.y);
    }
}

// =====================================================================
// Kernel 2: hyperedge -> node.
// smem: as [64][320] (aliased by gs [64][256] after GEMM1) + ws [16][256] + ids
// =====================================================================
__global__ __launch_bounds__(256, 2)
void k_e2n(const int*   __restrict__ node_ids,
           const int*   __restrict__ he_ids,
           const float* __restrict__ he_attr,
           const float* __restrict__ he_count,
           const float* __restrict__ w1, const float* __restrict__ b1,
           const float* __restrict__ lng, const float* __restrict__ lnb,
           const float* __restrict__ w2, const float* __restrict__ b2)
{
    extern __shared__ char smem_raw[];
    float* as = (float*)smem_raw;            // [64][320]; gs aliases after GEMM1
    float* ws = as + ROWS * DIN_;            // [16][256]
    int*   eid_s = (int*)(ws + KB * DH_);    // [64]
    int*   nid_s = eid_s + ROWS;             // [64]
    float* rc_s  = (float*)(nid_s + ROWS);   // [64]
    float* gs = as;                          // [64][256] alias

    const int tid = threadIdx.x;
    const int ty = tid >> 5, tx = tid & 31;
    const int m0 = blockIdx.x * ROWS;

    if (tid < ROWS) {
        int e = he_ids[m0 + tid];
        eid_s[tid] = e;
        nid_s[tid] = node_ids[m0 + tid];
        rc_s[tid]  = 1.f / (he_count[e] + 1e-6f);
    }
    __syncthreads();

    // gather he_attr part (64 cols)
    for (int i = tid; i < ROWS * (DHA_ / 4); i += 256) {
        int r = i >> 4, c4 = i & 15;
        float4 v = __ldg((const float4*)&he_attr[(size_t)eid_s[r] * DHA_ + c4 * 4]);
        *(float4*)&as[r * DIN_ + c4 * 4] = v;
    }
    // gather normalized agg part (256 cols)
    for (int i = tid; i < ROWS * (DH_ / 4); i += 256) {
        int r = i >> 6, c4 = i & 63;
        float rc = rc_s[r];
        float4 v = *(const float4*)&g_agg[(size_t)eid_s[r] * DH_ + c4 * 4];
        v.x *= rc; v.y *= rc; v.z *= rc; v.w *= rc;
        *(float4*)&as[r * DIN_ + DHA_ + c4 * 4] = v;
    }
    __syncthreads();

    u64 acc[8][4];

    // GEMM1: g = as @ w1 + b1  (K = 320)
    init_bias(b1, tx, acc);
    gemm_tile<DIN_, DIN_>(as, w1, ws, acc, tid, ty, tx);
    __syncthreads();   // done reading 'as' before alias-overwrite
    #pragma unroll
    for (int r = 0; r < 8; r++) {
        ulonglong2* dst = (ulonglong2*)&gs[(ty * 8 + r) * DH_ + tx * 8];
        dst[0] = make_ulonglong2(acc[r][0], acc[r][1]);
        dst[1] = make_ulonglong2(acc[r][2], acc[r][3]);
    }
    __syncthreads();

    ln_relu(gs, lng, lnb, tx, ty);
    __syncthreads();

    // GEMM2: msg = relu(gs @ w2 + b2) -> RED into g_acc (+ degree)
    init_bias(b2, tx, acc);
    gemm_tile<DH_, DH_>(gs, w2, ws, acc, tid, ty, tx);

    if (tx == 0) {
        #pragma unroll
        for (int r = 0; r < 8; r++)
            asm volatile("red.global.add.f32 [%0], %1;"
                         :: "l"(&g_deg[nid_s[ty * 8 + r]]), "f"(1.f) : "memory");
    }
    #pragma unroll
    for (int r = 0; r < 8; r++) {
        int n = nid_s[ty * 8 + r];
        float* dst = &g_acc[(size_t)n * DN_ + tx * 8];
        float2 p0 = upk(acc[r][0]), p1 = upk(acc[r][1]);
        float2 p2 = upk(acc[r][2]), p3 = upk(acc[r][3]);
        red4(dst,     fmaxf(p0.x, 0.f), fmaxf(p0.y, 0.f), fmaxf(p1.x, 0.f), fmaxf(p1.y, 0.f));
        red4(dst + 4, fmaxf(p2.x, 0.f), fmaxf(p2.y, 0.f), fmaxf(p3.x, 0.f), fmaxf(p3.y, 0.f));
    }
}

// =====================================================================
// Kernel 3: out = x + LN(g_acc / (deg + eps)).  Warp per node row.
// =====================================================================
__global__ __launch_bounds__(256, 4)
void k_final(const float* __restrict__ x,
             const float* __restrict__ lng, const float* __restrict__ lnb,
             float* __restrict__ out)
{
    const int lane = threadIdx.x & 31;
    const int n = blockIdx.x * 8 + (threadIdx.x >> 5);
    if (n >= NN) return;

    float rd = 1.f / (g_deg[n] + 1e-6f);
    float v[8], s = 0.f, sq = 0.f;
    #pragma unroll
    for (int j = 0; j < 8; j++) {
        v[j] = g_acc[(size_t)n * DN_ + lane + j * 32] * rd;
        s += v[j]; sq += v[j] * v[j];
    }
    #pragma unroll
    for (int o = 16; o; o >>= 1) {
        s  += __shfl_xor_sync(0xffffffffu, s, o);
        sq += __shfl_xor_sync(0xffffffffu, sq, o);
    }
    float mu = s * (1.f / DN_);
    float var = sq * (1.f / DN_) - mu * mu;
    float rs = rsqrtf(var + 1e-5f);
    #pragma unroll
    for (int j = 0; j < 8; j++) {
        int c = lane + j * 32;
        float t = (v[j] - mu) * rs * __ldg(&lng[c]) + __ldg(&lnb[c]);
        out[(size_t)n * DN_ + c] = __ldg(&x[(size_t)n * DN_ + c]) + t;
    }
}

// =====================================================================
// launcher
// =====================================================================
extern "C" void kernel_launch(void* const* d_in, const int* in_sizes, int n_in,
                              void* d_out, int out_size)
{
    const float* x        = (const float*)d_in[0];
    const int*   node_ids = (const int*)  d_in[1];
    const int*   he_ids   = (const int*)  d_in[2];
    const float* he_attr  = (const float*)d_in[3];
    const float* he_count = (const float*)d_in[4];
    const float* n2e_w1   = (const float*)d_in[5];
    const float* n2e_b1   = (const float*)d_in[6];
    const float* n2e_lng  = (const float*)d_in[7];
    const float* n2e_lnb  = (const float*)d_in[8];
    const float* n2e_w2   = (const float*)d_in[9];
    const float* n2e_b2   = (const float*)d_in[10];
    const float* e2n_w1   = (const float*)d_in[11];
    const float* e2n_b1   = (const float*)d_in[12];
    const float* e2n_lng  = (const float*)d_in[13];
    const float* e2n_lnb  = (const float*)d_in[14];
    const float* e2n_w2   = (const float*)d_in[15];
    const float* e2n_b2   = (const float*)d_in[16];
    const float* ln_g     = (const float*)d_in[17];
    const float* ln_b     = (const float*)d_in[18];
    float* out = (float*)d_out;

    void *p_agg, *p_acc, *p_deg;
    cudaGetSymbolAddress(&p_agg, g_agg);
    cudaGetSymbolAddress(&p_acc, g_acc);
    cudaGetSymbolAddress(&p_deg, g_deg);
    cudaMemsetAsync(p_agg, 0, sizeof(float) * (size_t)EE * DH_);
    cudaMemsetAsync(p_acc, 0, sizeof(float) * (size_t)NN * DN_);
    cudaMemsetAsync(p_deg, 0, sizeof(float) * NN);

    // dynamic smem sizes (fit 2 CTAs/SM)
    const int smem1 = (ROWS * DN_  + KB * DH_) * 4 + 2 * ROWS * 4;   // ~80.5 KB
    const int smem2 = (ROWS * DIN_ + KB * DH_) * 4 + 3 * ROWS * 4;   // ~96.8 KB
    cudaFuncSetAttribute(k_n2e, cudaFuncAttributeMaxDynamicSharedMemorySize, smem1);
    cudaFuncSetAttribute(k_e2n, cudaFuncAttributeMaxDynamicSharedMemorySize, smem2);

    k_n2e<<<MM / ROWS, 256, smem1>>>(x, node_ids, he_ids,
                                     n2e_w1, n2e_b1, n2e_lng, n2e_lnb, n2e_w2, n2e_b2);
    k_e2n<<<MM / ROWS, 256, smem2>>>(node_ids, he_ids, he_attr, he_count,
                                     e2n_w1, e2n_b1, e2n_lng, e2n_lnb, e2n_w2, e2n_b2);
    k_final<<<(NN + 7) / 8, 256>>>(x, ln_g, ln_b, out);
}

// round 6
// speedup vs baseline: 2.8893x; 1.9994x over previous
#include <cuda_runtime.h>
#include <cuda_bf16.h>
#include <cstdint>

// ---------------- problem constants ----------------
#define NN   50000
#define MM   200000
#define EE   10000
#define DN_  256
#define DHA_ 64
#define DH_  256
#define DIN_ 320

#define MT   128          // rows per block
#define KC   64           // K chunk (one SW128 tile)
#define TILE_B (MT * 128) // bytes of one [128][64] bf16 tile = 16384

#define GRID1 ((MM + MT - 1) / MT)   // 1563

typedef unsigned long long u64;

// ---------------- device scratch ----------------
__device__ float g_agg[(size_t)EE * DH_];
__device__ float g_acc[(size_t)NN * DN_];
__device__ float g_deg[NN];

// transposed bf16 hi/lo weights: [N][K]
__device__ __nv_bfloat16 g_wa_hi[DN_ * DH_], g_wa_lo[DN_ * DH_];   // n2e_w1^T [256][256]
__device__ __nv_bfloat16 g_wb_hi[DH_ * DH_], g_wb_lo[DH_ * DH_];   // n2e_w2^T [256][256]
__device__ __nv_bfloat16 g_wc_hi[DH_ * DIN_], g_wc_lo[DH_ * DIN_]; // e2n_w1^T [256][320]
__device__ __nv_bfloat16 g_wd_hi[DN_ * DH_], g_wd_lo[DN_ * DH_];   // e2n_w2^T [256][256]

// ---------------- helpers ----------------
__device__ __forceinline__ uint32_t s2u(const void* p) {
    uint32_t a;
    asm("{ .reg .u64 t; cvta.to.shared.u64 t, %1; cvt.u32.u64 %0, t; }" : "=r"(a) : "l"(p));
    return a;
}
#define SW128(x) ((x) ^ ((((x) >> 3) & 0x70)))

__device__ __forceinline__ void ldsm4(uint32_t* r, uint32_t a) {
    asm volatile("ldmatrix.sync.aligned.m8n8.x4.shared.b16 {%0,%1,%2,%3}, [%4];"
        : "=r"(r[0]), "=r"(r[1]), "=r"(r[2]), "=r"(r[3]) : "r"(a));
}
__device__ __forceinline__ void mma16816(float* d, const uint32_t* a, const uint32_t* b) {
    asm volatile("mma.sync.aligned.m16n8k16.row.col.f32.bf16.bf16.f32 "
        "{%0,%1,%2,%3}, {%4,%5,%6,%7}, {%8,%9}, {%0,%1,%2,%3};"
        : "+f"(d[0]), "+f"(d[1]), "+f"(d[2]), "+f"(d[3])
        : "r"(a[0]), "r"(a[1]), "r"(a[2]), "r"(a[3]), "r"(b[0]), "r"(b[1]));
}
__device__ __forceinline__ void red2(float* p, float a, float b) {
    asm volatile("red.global.add.v2.f32 [%0], {%1, %2};" :: "l"(p), "f"(a), "f"(b) : "memory");
}

// pack 2 floats -> bf16x2 (first arg -> low half / lower address)
__device__ __forceinline__ uint32_t pkbf(float lo, float hi) {
    uint32_t r;
    asm("cvt.rn.bf16x2.f32 %0, %1, %2;" : "=r"(r) : "f"(hi), "f"(lo));
    return r;
}
// convert float4 -> hi u64 (4 bf16) and lo u64 (residual)
__device__ __forceinline__ void cvt4(float4 v, u64& hi, u64& lo) {
    float hx = __bfloat162float(__float2bfloat16(v.x));
    float hy = __bfloat162float(__float2bfloat16(v.y));
    float hz = __bfloat162float(__float2bfloat16(v.z));
    float hw = __bfloat162float(__float2bfloat16(v.w));
    uint32_t h01 = pkbf(hx, hy), h23 = pkbf(hz, hw);
    uint32_t l01 = pkbf(v.x - hx, v.y - hy), l23 = pkbf(v.z - hz, v.w - hw);
    hi = (u64)h01 | ((u64)h23 << 32);
    lo = (u64)l01 | ((u64)l23 << 32);
}

// stage one B chunk [256 n][64 k] bf16 (hi and lo) into swizzled smem
__device__ __forceinline__ void load_B(const __nv_bfloat16* __restrict__ wh,
                                       const __nv_bfloat16* __restrict__ wl,
                                       int kc, int kstride,
                                       char* bH, char* bL, int tid)
{
    for (int i = tid; i < 256 * 16; i += 256) {
        int n = i >> 4, q = i & 15;
        size_t src = (size_t)n * kstride + kc * KC + q * 4;
        u64 vh = *(const u64*)&wh[src];
        u64 vl = *(const u64*)&wl[src];
        uint32_t off = SW128((uint32_t)(n * 128 + q * 8));
        *(u64*)(bH + off) = vh;
        *(u64*)(bL + off) = vl;
    }
}

// ---------------- MMA compute for one K-chunk (3 split terms) ----------------
// acc[4][8][4]: warp tile 64x64 (4 m16 tiles x 8 n8 tiles)
__device__ __forceinline__ void gemm_chunk(uint32_t aH, uint32_t aL,
                                           uint32_t bH, uint32_t bL,
                                           float (*acc)[8][4],
                                           int lane, int m_base, int n_base)
{
    const uint32_t swz  = (uint32_t)(lane & 7) << 4;
    const uint32_t arow = (uint32_t)(m_base + (lane & 15)) * 128;
    const uint32_t aka  = (uint32_t)((lane >> 4) << 3) * 2;
    const uint32_t brow = (uint32_t)(n_base + ((lane >> 4) << 3) + (lane & 7)) * 128;
    const uint32_t bka  = (uint32_t)(((lane >> 3) & 1) << 3) * 2;

    #pragma unroll
    for (int ks = 0; ks < 4; ks++) {
        const uint32_t koff = ks * 32;
        const uint32_t aoff = arow + ((koff + aka) ^ swz);
        const uint32_t boff = brow + ((koff + bka) ^ swz);
        uint32_t fa[4][4], fb[4][4], f2[4][4];
        #pragma unroll
        for (int mi = 0; mi < 4; mi++) ldsm4(fa[mi], aH + aoff + mi * 2048);
        #pragma unroll
        for (int j = 0; j < 4; j++)  ldsm4(fb[j], bH + boff + j * 2048);
        #pragma unroll
        for (int mi = 0; mi < 4; mi++)
            #pragma unroll
            for (int j = 0; j < 4; j++) {
                mma16816(acc[mi][2 * j],     fa[mi], fb[j]);
                mma16816(acc[mi][2 * j + 1], fa[mi], fb[j] + 2);
            }
        // aL * bH
        #pragma unroll
        for (int mi = 0; mi < 4; mi++) ldsm4(f2[mi], aL + aoff + mi * 2048);
        #pragma unroll
        for (int mi = 0; mi < 4; mi++)
            #pragma unroll
            for (int j = 0; j < 4; j++) {
                mma16816(acc[mi][2 * j],     f2[mi], fb[j]);
                mma16816(acc[mi][2 * j + 1], f2[mi], fb[j] + 2);
            }
        // aH * bL (reuse fb)
        #pragma unroll
        for (int j = 0; j < 4; j++)  ldsm4(fb[j], bL + boff + j * 2048);
        #pragma unroll
        for (int mi = 0; mi < 4; mi++)
            #pragma unroll
            for (int j = 0; j < 4; j++) {
                mma16816(acc[mi][2 * j],     fa[mi], fb[j]);
                mma16816(acc[mi][2 * j + 1], fa[mi], fb[j] + 2);
            }
    }
}

__device__ __forceinline__ void init_bias_reg(float (*acc)[8][4],
                                              const float* __restrict__ b,
                                              int lane, int n_base)
{
    #pragma unroll
    for (int ni = 0; ni < 8; ni++) {
        int c = n_base + ni * 8 + 2 * (lane & 3);
        float v0 = __ldg(&b[c]), v1 = __ldg(&b[c + 1]);
        #pragma unroll
        for (int mi = 0; mi < 4; mi++) {
            acc[mi][ni][0] = v0; acc[mi][ni][1] = v1;
            acc[mi][ni][2] = v0; acc[mi][ni][3] = v1;
        }
    }
}

// LayerNorm + ReLU on register accumulators -> bf16 hi/lo into A2 smem tiles.
// Row partials reduced quad-wise then across warp_n slices via ps[128][4] (x2).
__device__ __forceinline__ void ln_apply(float (*acc)[8][4],
                                         const float* __restrict__ lng,
                                         const float* __restrict__ lnb,
                                         char* a2H, char* a2L, float* ps,
                                         int lane, int m_base, int n_base, int warp_n)
{
    #pragma unroll
    for (int mi = 0; mi < 4; mi++) {
        float sl = 0.f, ql = 0.f, sh = 0.f, qh = 0.f;
        #pragma unroll
        for (int ni = 0; ni < 8; ni++) {
            float a0 = acc[mi][ni][0], a1 = acc[mi][ni][1];
            float a2 = acc[mi][ni][2], a3 = acc[mi][ni][3];
            sl += a0 + a1; ql += a0 * a0 + a1 * a1;
            sh += a2 + a3; qh += a2 * a2 + a3 * a3;
        }
        sl += __shfl_xor_sync(0xffffffffu, sl, 1); sl += __shfl_xor_sync(0xffffffffu, sl, 2);
        ql += __shfl_xor_sync(0xffffffffu, ql, 1); ql += __shfl_xor_sync(0xffffffffu, ql, 2);
        sh += __shfl_xor_sync(0xffffffffu, sh, 1); sh += __shfl_xor_sync(0xffffffffu, sh, 2);
        qh += __shfl_xor_sync(0xffffffffu, qh, 1); qh += __shfl_xor_sync(0xffffffffu, qh, 2);
        if ((lane & 3) == 0) {
            int rl = m_base + mi * 16 + (lane >> 2);
            ps[rl * 4 + warp_n] = sl;        ps[512 + rl * 4 + warp_n] = ql;
            ps[(rl + 8) * 4 + warp_n] = sh;  ps[512 + (rl + 8) * 4 + warp_n] = qh;
        }
    }
    __syncthreads();
    float mu[4][2], rsd[4][2];
    #pragma unroll
    for (int mi = 0; mi < 4; mi++) {
        int rl = m_base + mi * 16 + (lane >> 2);
        #pragma unroll
        for (int h = 0; h < 2; h++) {
            int r = rl + h * 8;
            float s = ps[r * 4] + ps[r * 4 + 1] + ps[r * 4 + 2] + ps[r * 4 + 3];
            float q = ps[512 + r * 4] + ps[512 + r * 4 + 1] + ps[512 + r * 4 + 2] + ps[512 + r * 4 + 3];
            float m = s * (1.f / 256.f);
            float var = q * (1.f / 256.f) - m * m;
            mu[mi][h] = m;
            rsd[mi][h] = rsqrtf(var + 1e-5f);
        }
    }
    __syncthreads();   // ps region free for B reload
    #pragma unroll
    for (int mi = 0; mi < 4; mi++) {
        int rl = m_base + mi * 16 + (lane >> 2);
        int rh = rl + 8;
        uint32_t rswz = (uint32_t)(lane >> 2) << 4;   // (row&7)<<4, same for rl/rh
        #pragma unroll
        for (int ni = 0; ni < 8; ni++) {
            int cl = ni * 8 + 2 * (lane & 3);
            int c  = n_base + cl;
            float g0 = __ldg(&lng[c]),  g1 = __ldg(&lng[c + 1]);
            float B0 = __ldg(&lnb[c]),  B1 = __ldg(&lnb[c + 1]);
            uint32_t kb = ((uint32_t)(cl * 2)) ^ rswz;
            // row rl
            {
                float t0 = fmaxf((acc[mi][ni][0] - mu[mi][0]) * rsd[mi][0] * g0 + B0, 0.f);
                float t1 = fmaxf((acc[mi][ni][1] - mu[mi][0]) * rsd[mi][0] * g1 + B1, 0.f);
                float h0 = __bfloat162float(__float2bfloat16(t0));
                float h1 = __bfloat162float(__float2bfloat16(t1));
                uint32_t off = (uint32_t)warp_n * TILE_B + (uint32_t)rl * 128 + kb;
                *(uint32_t*)(a2H + off) = pkbf(h0, h1);
                *(uint32_t*)(a2L + off) = pkbf(t0 - h0, t1 - h1);
            }
            // row rh
            {
                float t0 = fmaxf((acc[mi][ni][2] - mu[mi][1]) * rsd[mi][1] * g0 + B0, 0.f);
                float t1 = fmaxf((acc[mi][ni][3] - mu[mi][1]) * rsd[mi][1] * g1 + B1, 0.f);
                float h0 = __bfloat162float(__float2bfloat16(t0));
                float h1 = __bfloat162float(__float2bfloat16(t1));
                uint32_t off = (uint32_t)warp_n * TILE_B + (uint32_t)rh * 128 + kb;
                *(uint32_t*)(a2H + off) = pkbf(h0, h1);
                *(uint32_t*)(a2L + off) = pkbf(t0 - h0, t1 - h1);
            }
        }
    }
}

// ---------------- prep: transpose weights to bf16 hi/lo [N][K] ----------------
__global__ void k_prep(const float* __restrict__ w, __nv_bfloat16* th, __nv_bfloat16* tl,
                       int K, int N)
{
    int i = blockIdx.x * 256 + threadIdx.x;
    if (i >= K * N) return;
    int n = i / K, k = i - n * K;
    float v = __ldg(&w[(size_t)k * N + n]);
    __nv_bfloat16 h = __float2bfloat16(v);
    th[i] = h;
    tl[i] = __float2bfloat16(v - __bfloat162float(h));
}

// ---------------- smem offsets ----------------
#define K1_AHI 0
#define K1_ALO 65536
#define K1_BHI 131072
#define K1_BLO 163840
#define K1_EID 196608
#define K1_NID 197120
#define K1_SMEM 197664

#define K2_AHI 0
#define K2_ALO 81920
#define K2_BHI 163840
#define K2_BLO 196608
#define K2_EID 229376
#define K2_NID 229888
#define K2_RC  230400
#define K2_SMEM 230944

// =====================================================================
// Kernel 1: node -> hyperedge (mma.sync tensor path)
// =====================================================================
__global__ __launch_bounds__(256, 1)
void k_n2e(const float* __restrict__ x,
           const int*   __restrict__ node_ids,
           const int*   __restrict__ he_ids,
           const float* __restrict__ b1,
           const float* __restrict__ lng, const float* __restrict__ lnb,
           const float* __restrict__ b2)
{
    extern __shared__ char sm[];
    const uint32_t smb = s2u(sm);
    const int tid = threadIdx.x, wid = tid >> 5, lane = tid & 31;
    const int warp_m = wid >> 2, warp_n = wid & 3;
    const int m_base = warp_m * 64, n_base = warp_n * 64;
    const int m0 = blockIdx.x * MT;

    int* eid_s = (int*)(sm + K1_EID);
    int* nid_s = (int*)(sm + K1_NID);
    float* ps  = (float*)(sm + K1_BHI);   // LN partials alias B (dead between GEMMs)

    if (tid < MT) {
        int m = m0 + tid;
        int mc = m < MM ? m : MM - 1;
        eid_s[tid] = he_ids[mc];
        nid_s[tid] = node_ids[mc];
    }
    __syncthreads();

    // gather x -> bf16 hi/lo swizzled A tiles
    for (int i = tid; i < MT * 64; i += 256) {
        int r = i >> 6, c4 = i & 63;
        float4 v = __ldg((const float4*)&x[(size_t)nid_s[r] * DN_ + c4 * 4]);
        u64 hi, lo; cvt4(v, hi, lo);
        int k = c4 * 4, tile = k >> 6, kin = k & 63;
        uint32_t off = tile * TILE_B + SW128((uint32_t)(r * 128 + kin * 2));
        *(u64*)(sm + K1_AHI + off) = hi;
        *(u64*)(sm + K1_ALO + off) = lo;
    }

    float acc[4][8][4];
    init_bias_reg(acc, b1, lane, n_base);
    __syncthreads();

    // ---- GEMM1: D = X @ W1 ----
    #pragma unroll 1
    for (int kc = 0; kc < DN_ / KC; kc++) {
        load_B(g_wa_hi, g_wa_lo, kc, DN_, sm + K1_BHI, sm + K1_BLO, tid);
        __syncthreads();
        gemm_chunk(smb + K1_AHI + kc * TILE_B, smb + K1_ALO + kc * TILE_B,
                   smb + K1_BHI, smb + K1_BLO, acc, lane, m_base, n_base);
        __syncthreads();
    }

    // ---- LN + ReLU -> A2 tiles (alias A1) ----
    ln_apply(acc, lng, lnb, sm + K1_AHI, sm + K1_ALO, ps, lane, m_base, n_base, warp_n);
    init_bias_reg(acc, b2, lane, n_base);
    __syncthreads();

    // ---- GEMM2: D = H @ W2 ----
    #pragma unroll 1
    for (int kc = 0; kc < DH_ / KC; kc++) {
        load_B(g_wb_hi, g_wb_lo, kc, DH_, sm + K1_BHI, sm + K1_BLO, tid);
        __syncthreads();
        gemm_chunk(smb + K1_AHI + kc * TILE_B, smb + K1_ALO + kc * TILE_B,
                   smb + K1_BHI, smb + K1_BLO, acc, lane, m_base, n_base);
        __syncthreads();
    }

    // ---- epilogue: scatter-add to g_agg (bias already in acc) ----
    #pragma unroll
    for (int mi = 0; mi < 4; mi++) {
        int rl = m_base + mi * 16 + (lane >> 2);
        int rh = rl + 8;
        if (m0 + rl < MM) {
            int e = eid_s[rl];
            #pragma unroll
            for (int ni = 0; ni < 8; ni++) {
                int c = n_base + ni * 8 + 2 * (lane & 3);
                red2(&g_agg[(size_t)e * DH_ + c], acc[mi][ni][0], acc[mi][ni][1]);
            }
        }
        if (m0 + rh < MM) {
            int e = eid_s[rh];
            #pragma unroll
            for (int ni = 0; ni < 8; ni++) {
                int c = n_base + ni * 8 + 2 * (lane & 3);
                red2(&g_agg[(size_t)e * DH_ + c], acc[mi][ni][2], acc[mi][ni][3]);
            }
        }
    }
}

// =====================================================================
// Kernel 2: hyperedge -> node (mma.sync), GEMM1 K = 320
// =====================================================================
__global__ __launch_bounds__(256, 1)
void k_e2n(const int*   __restrict__ node_ids,
           const int*   __restrict__ he_ids,
           const float* __restrict__ he_attr,
           const float* __restrict__ he_count,
           const float* __restrict__ b1,
           const float* __restrict__ lng, const float* __restrict__ lnb,
           const float* __restrict__ b2)
{
    extern __shared__ char sm[];
    const uint32_t smb = s2u(sm);
    const int tid = threadIdx.x, wid = tid >> 5, lane = tid & 31;
    const int warp_m = wid >> 2, warp_n = wid & 3;
    const int m_base = warp_m * 64, n_base = warp_n * 64;
    const int m0 = blockIdx.x * MT;

    int* eid_s = (int*)(sm + K2_EID);
    int* nid_s = (int*)(sm + K2_NID);
    float* rc_s = (float*)(sm + K2_RC);
    float* ps  = (float*)(sm + K2_BHI);

    if (tid < MT) {
        int m = m0 + tid;
        int mc = m < MM ? m : MM - 1;
        int e = he_ids[mc];
        eid_s[tid] = e;
        nid_s[tid] = node_ids[mc];
        rc_s[tid]  = 1.f / (__ldg(&he_count[e]) + 1e-6f);
    }
    __syncthreads();

    // gather [he_attr | agg/cnt] -> bf16 hi/lo swizzled A tiles (5 tiles)
    for (int i = tid; i < MT * 16; i += 256) {            // attr: k 0..63 (tile 0)
        int r = i >> 4, q = i & 15;
        float4 v = __ldg((const float4*)&he_attr[(size_t)eid_s[r] * DHA_ + q * 4]);
        u64 hi, lo; cvt4(v, hi, lo);
        uint32_t off = SW128((uint32_t)(r * 128 + q * 8));
        *(u64*)(sm + K2_AHI + off) = hi;
        *(u64*)(sm + K2_ALO + off) = lo;
    }
    for (int i = tid; i < MT * 64; i += 256) {            // agg: k 64..319 (tiles 1-4)
        int r = i >> 6, c4 = i & 63;
        float rc = rc_s[r];
        float4 v = *(const float4*)&g_agg[(size_t)eid_s[r] * DH_ + c4 * 4];
        v.x *= rc; v.y *= rc; v.z *= rc; v.w *= rc;
        u64 hi, lo; cvt4(v, hi, lo);
        int k = 64 + c4 * 4, tile = k >> 6, kin = k & 63;
        uint32_t off = tile * TILE_B + SW128((uint32_t)(r * 128 + kin * 2));
        *(u64*)(sm + K2_AHI + off) = hi;
        *(u64*)(sm + K2_ALO + off) = lo;
    }

    float acc[4][8][4];
    init_bias_reg(acc, b1, lane, n_base);
    __syncthreads();

    // ---- GEMM1: D = [attr|agg] @ W1, K = 320 ----
    #pragma unroll 1
    for (int kc = 0; kc < DIN_ / KC; kc++) {
        load_B(g_wc_hi, g_wc_lo, kc, DIN_, sm + K2_BHI, sm + K2_BLO, tid);
        __syncthreads();
        gemm_chunk(smb + K2_AHI + kc * TILE_B, smb + K2_ALO + kc * TILE_B,
                   smb + K2_BHI, smb + K2_BLO, acc, lane, m_base, n_base);
        __syncthreads();
    }

    // ---- LN + ReLU -> A2 tiles (alias A1 tiles 0-3) ----
    ln_apply(acc, lng, lnb, sm + K2_AHI, sm + K2_ALO, ps, lane, m_base, n_base, warp_n);
    init_bias_reg(acc, b2, lane, n_base);
    __syncthreads();

    // ---- GEMM2: D = G @ W2, K = 256 ----
    #pragma unroll 1
    for (int kc = 0; kc < DH_ / KC; kc++) {
        load_B(g_wd_hi, g_wd_lo, kc, DH_, sm + K2_BHI, sm + K2_BLO, tid);
        __syncthreads();
        gemm_chunk(smb + K2_AHI + kc * TILE_B, smb + K2_ALO + kc * TILE_B,
                   smb + K2_BHI, smb + K2_BLO, acc, lane, m_base, n_base);
        __syncthreads();
    }

    // ---- epilogue: relu(D) scatter-add to g_acc + degree ----
    #pragma unroll
    for (int mi = 0; mi < 4; mi++) {
        int rl = m_base + mi * 16 + (lane >> 2);
        int rh = rl + 8;
        if (m0 + rl < MM) {
            int n = nid_s[rl];
            #pragma unroll
            for (int ni = 0; ni < 8; ni++) {
                int c = n_base + ni * 8 + 2 * (lane & 3);
                red2(&g_acc[(size_t)n * DN_ + c],
                     fmaxf(acc[mi][ni][0], 0.f), fmaxf(acc[mi][ni][1], 0.f));
            }
            if (warp_n == 0 && (lane & 3) == 0)
                asm volatile("red.global.add.f32 [%0], %1;" :: "l"(&g_deg[n]), "f"(1.f) : "memory");
        }
        if (m0 + rh < MM) {
            int n = nid_s[rh];
            #pragma unroll
            for (int ni = 0; ni < 8; ni++) {
                int c = n_base + ni * 8 + 2 * (lane & 3);
                red2(&g_acc[(size_t)n * DN_ + c],
                     fmaxf(acc[mi][ni][2], 0.f), fmaxf(acc[mi][ni][3], 0.f));
            }
            if (warp_n == 0 && (lane & 3) == 0)
                asm volatile("red.global.add.f32 [%0], %1;" :: "l"(&g_deg[n]), "f"(1.f) : "memory");
        }
    }
}

// =====================================================================
// Kernel 3: out = x + LN(g_acc / (deg + eps)).  Warp per node row.
// =====================================================================
__global__ __launch_bounds__(256, 4)
void k_final(const float* __restrict__ x,
             const float* __restrict__ lng, const float* __restrict__ lnb,
             float* __restrict__ out)
{
    const int lane = threadIdx.x & 31;
    const int n = blockIdx.x * 8 + (threadIdx.x >> 5);
    if (n >= NN) return;

    float rd = 1.f / (g_deg[n] + 1e-6f);
    float v[8], s = 0.f, sq = 0.f;
    #pragma unroll
    for (int j = 0; j < 8; j++) {
        v[j] = g_acc[(size_t)n * DN_ + lane + j * 32] * rd;
        s += v[j]; sq += v[j] * v[j];
    }
    #pragma unroll
    for (int o = 16; o; o >>= 1) {
        s  += __shfl_xor_sync(0xffffffffu, s, o);
        sq += __shfl_xor_sync(0xffffffffu, sq, o);
    }
    float mu = s * (1.f / DN_);
    float var = sq * (1.f / DN_) - mu * mu;
    float rs = rsqrtf(var + 1e-5f);
    #pragma unroll
    for (int j = 0; j < 8; j++) {
        int c = lane + j * 32;
        float t = (v[j] - mu) * rs * __ldg(&lng[c]) + __ldg(&lnb[c]);
        out[(size_t)n * DN_ + c] = __ldg(&x[(size_t)n * DN_ + c]) + t;
    }
}

// =====================================================================
// launcher
// =====================================================================
extern "C" void kernel_launch(void* const* d_in, const int* in_sizes, int n_in,
                              void* d_out, int out_size)
{
    const float* x        = (const float*)d_in[0];
    const int*   node_ids = (const int*)  d_in[1];
    const int*   he_ids   = (const int*)  d_in[2];
    const float* he_attr  = (const float*)d_in[3];
    const float* he_count = (const float*)d_in[4];
    const float* n2e_w1   = (const float*)d_in[5];
    const float* n2e_b1   = (const float*)d_in[6];
    const float* n2e_lng  = (const float*)d_in[7];
    const float* n2e_lnb  = (const float*)d_in[8];
    const float* n2e_w2   = (const float*)d_in[9];
    const float* n2e_b2   = (const float*)d_in[10];
    const float* e2n_w1   = (const float*)d_in[11];
    const float* e2n_b1   = (const float*)d_in[12];
    const float* e2n_lng  = (const float*)d_in[13];
    const float* e2n_lnb  = (const float*)d_in[14];
    const float* e2n_w2   = (const float*)d_in[15];
    const float* e2n_b2   = (const float*)d_in[16];
    const float* ln_g     = (const float*)d_in[17];
    const float* ln_b     = (const float*)d_in[18];
    float* out = (float*)d_out;

    void *p_agg, *p_acc, *p_deg;
    cudaGetSymbolAddress(&p_agg, g_agg);
    cudaGetSymbolAddress(&p_acc, g_acc);
    cudaGetSymbolAddress(&p_deg, g_deg);
    cudaMemsetAsync(p_agg, 0, sizeof(float) * (size_t)EE * DH_);
    cudaMemsetAsync(p_acc, 0, sizeof(float) * (size_t)NN * DN_);
    cudaMemsetAsync(p_deg, 0, sizeof(float) * NN);

    void *wa_h, *wa_l, *wb_h, *wb_l, *wc_h, *wc_l, *wd_h, *wd_l;
    cudaGetSymbolAddress(&wa_h, g_wa_hi); cudaGetSymbolAddress(&wa_l, g_wa_lo);
    cudaGetSymbolAddress(&wb_h, g_wb_hi); cudaGetSymbolAddress(&wb_l, g_wb_lo);
    cudaGetSymbolAddress(&wc_h, g_wc_hi); cudaGetSymbolAddress(&wc_l, g_wc_lo);
    cudaGetSymbolAddress(&wd_h, g_wd_hi); cudaGetSymbolAddress(&wd_l, g_wd_lo);

    k_prep<<<(DN_ * DH_ + 255) / 256, 256>>>(n2e_w1, (__nv_bfloat16*)wa_h, (__nv_bfloat16*)wa_l, DN_, DH_);
    k_prep<<<(DH_ * DH_ + 255) / 256, 256>>>(n2e_w2, (__nv_bfloat16*)wb_h, (__nv_bfloat16*)wb_l, DH_, DH_);
    k_prep<<<(DIN_ * DH_ + 255) / 256, 256>>>(e2n_w1, (__nv_bfloat16*)wc_h, (__nv_bfloat16*)wc_l, DIN_, DH_);
    k_prep<<<(DH_ * DN_ + 255) / 256, 256>>>(e2n_w2, (__nv_bfloat16*)wd_h, (__nv_bfloat16*)wd_l, DH_, DN_);

    cudaFuncSetAttribute(k_n2e, cudaFuncAttributeMaxDynamicSharedMemorySize, K1_SMEM);
    cudaFuncSetAttribute(k_e2n, cudaFuncAttributeMaxDynamicSharedMemorySize, K2_SMEM);

    k_n2e<<<GRID1, 256, K1_SMEM>>>(x, node_ids, he_ids,
                                   n2e_b1, n2e_lng, n2e_lnb, n2e_b2);
    k_e2n<<<GRID1, 256, K2_SMEM>>>(node_ids, he_ids, he_attr, he_count,
                                   e2n_b1, e2n_lng, e2n_lnb, e2n_b2);
    k_final<<<(NN + 7) / 8, 256>>>(x, ln_g, ln_b, out);
}